// round 11
// baseline (speedup 1.0000x reference)
#include <cuda_runtime.h>
#include <cuda_fp16.h>
#include <cstdint>

#define HID 1024
#define HEADS 8
#define DD 128
#define NSEG 16
#define SEGLEN 256
#define EE_N 16
#define II 512
#define NGROUP 512
#define MROWS 16384
#define SS_ 4096

__device__ __half g_xb[MROWS * HID];
__device__ __half g_wmh[HID * HID];
__device__ __half g_wmg[HID * HID];
__device__ __half g_xh[MROWS * HID];
__device__ float  g_ew[NGROUP * EE_N];
__device__ __half g_m1[NGROUP * II * DD];
__device__ __half g_m2[NGROUP * DD * II];
__device__ __half g_h[NGROUP * SEGLEN * II];
__device__ __half g_y2[MROWS * HID];

__device__ __forceinline__ uint32_t smem_u32(const void* p) {
    uint32_t a;
    asm("{ .reg .u64 t; cvta.to.shared.u64 t, %1; cvt.u32.u64 %0, t; }" : "=r"(a) : "l"(p));
    return a;
}
__device__ __forceinline__ void cp_async16(uint32_t dst, const void* src) {
    asm volatile("cp.async.cg.shared.global [%0], [%1], 16;" :: "r"(dst), "l"(src) : "memory");
}

#define LDSM4(r, ad) \
    asm volatile("ldmatrix.sync.aligned.m8n8.x4.shared.b16 {%0,%1,%2,%3}, [%4];" \
        : "=r"((r)[0]), "=r"((r)[1]), "=r"((r)[2]), "=r"((r)[3]) : "r"(ad))

#define MMA(c, a, b) \
    asm volatile("mma.sync.aligned.m16n8k16.row.col.f32.f16.f16.f32 " \
        "{%0,%1,%2,%3},{%4,%5,%6,%7},{%8,%9},{%0,%1,%2,%3};" \
        : "+f"((c)[0]), "+f"((c)[1]), "+f"((c)[2]), "+f"((c)[3]) \
        : "r"((a)[0]), "r"((a)[1]), "r"((a)[2]), "r"((a)[3]), "r"((b)[0]), "r"((b)[1]))

// K-chunk 64 (128B rows), pitch 144: (9r)%8 = r%8 -> 8 consecutive rows
// hit 8 distinct 16B slots mod 128B => conflict-free ldmatrix.
#define RPITCH 144
#define PLANE  (128 * RPITCH)          // 18432
#define STAGE  (2 * PLANE)             // 36864 (A plane + B plane)
#define NSTAGE 3
#define SMEM_BYTES (NSTAGE * STAGE)    // 110592; 2 CTAs/SM (221KB < 228KB, regs<=128)

#define COMMIT_EMPTY() asm volatile("cp.async.commit_group;" ::: "memory")

// C[128,128] += A * B^T over K; fp16 operands; fp32 accum.
// 8 warps, warp tile 64x32. K % 64 == 0. 3-stage ring, 1 sync/chunk.
__global__ __launch_bounds__(256)
void mma_gemm(const __half* __restrict__ A, const __half* __restrict__ B,
              __half* __restrict__ Ch, float* __restrict__ Cf,
              const float* __restrict__ bias,
              int K, int lda, int ldb, int ldc,
              long long aB, long long bB, long long cB, int doRelu)
{
    extern __shared__ char dsm[];
    const int tid  = threadIdx.x;
    const int lane = tid & 31;
    const int warp = tid >> 5;
    const int wm   = warp & 1;        // 0..1 : 64-row slab
    const int wn   = warp >> 1;       // 0..3 : 32-col slab

    const long long gz = blockIdx.z;
    A += gz * aB;
    B += gz * bB;
    const long long coff = gz * cB;
    const int m0 = blockIdx.y * 128;
    const int n0 = blockIdx.x * 128;

    const uint32_t sb = smem_u32(dsm);
    const int NK = K >> 6;

    float acc[4][4][4];
#pragma unroll
    for (int i = 0; i < 4; i++)
#pragma unroll
        for (int j = 0; j < 4; j++)
#pragma unroll
            for (int q = 0; q < 4; q++) acc[i][j][q] = 0.f;

    // cp.async: 2 planes x 128 rows x 8 chunks(16B) = 2048 chunks; 8 per thread
    const __half* srcP[8];
    uint32_t dstOff[8];
#pragma unroll
    for (int it = 0; it < 8; it++) {
        int idx = it * 256 + tid;
        int pl = idx >> 10;            // 0=A, 1=B
        int r  = (idx >> 3) & 127;
        int ch = idx & 7;
        srcP[it] = (pl ? B + (long long)(n0 + r) * ldb
                       : A + (long long)(m0 + r) * lda) + ch * 8;
        dstOff[it] = pl * PLANE + r * RPITCH + ch * 16;
    }

#define ISSUE(kt, st)                                                          \
    do {                                                                       \
        const int koff_ = (kt) << 6;                                           \
        const uint32_t db_ = sb + (st) * STAGE;                                \
        _Pragma("unroll")                                                      \
        for (int it = 0; it < 8; it++)                                         \
            cp_async16(db_ + dstOff[it], srcP[it] + koff_);                    \
        asm volatile("cp.async.commit_group;" ::: "memory");                   \
    } while (0)

    const int rowOffA = (lane & 7) + ((lane >> 3) & 1) * 8;
    const int kOffA   = ((lane >> 4) & 1) * 8;
    const int rowOffB = (lane & 7) + ((lane >> 4) & 1) * 8;
    const int kOffB   = ((lane >> 3) & 1) * 8;

    ISSUE(0, 0);
    if (NK > 1) { ISSUE(1, 1); } else { COMMIT_EMPTY(); }

    int stR = 0, stW = 2;
    for (int kt = 0; kt < NK; kt++) {
        asm volatile("cp.async.wait_group 1;" ::: "memory");
        __syncthreads();
        if (kt + 2 < NK) { ISSUE(kt + 2, stW); } else { COMMIT_EMPTY(); }

        const uint32_t base = sb + stR * STAGE;
#pragma unroll
        for (int ks = 0; ks < 4; ks++) {
            uint32_t a_f[4][4], b_f[4][2];
#pragma unroll
            for (int mt = 0; mt < 4; mt++) {
                uint32_t ad = base + (wm * 64 + mt * 16 + rowOffA) * RPITCH
                            + (ks * 16 + kOffA) * 2;
                LDSM4(a_f[mt], ad);
            }
#pragma unroll
            for (int pr = 0; pr < 2; pr++) {
                uint32_t bd = base + PLANE
                            + (wn * 32 + pr * 16 + rowOffB) * RPITCH
                            + (ks * 16 + kOffB) * 2;
                uint32_t r4[4];
                LDSM4(r4, bd);
                b_f[pr * 2][0] = r4[0];     b_f[pr * 2][1] = r4[1];
                b_f[pr * 2 + 1][0] = r4[2]; b_f[pr * 2 + 1][1] = r4[3];
            }
#pragma unroll
            for (int mt = 0; mt < 4; mt++)
#pragma unroll
                for (int nt = 0; nt < 4; nt++)
                    MMA(acc[mt][nt], a_f[mt], b_f[nt]);
        }
        stR = (stR == 2) ? 0 : stR + 1;
        stW = (stW == 2) ? 0 : stW + 1;
    }

    // epilogue
    const int rq = lane >> 2;
    const int cq = (lane & 3) * 2;
#pragma unroll
    for (int mt = 0; mt < 4; mt++)
#pragma unroll
        for (int nt = 0; nt < 4; nt++) {
            const int row = m0 + wm * 64 + mt * 16 + rq;
            const int col = n0 + wn * 32 + nt * 8 + cq;
            float b0 = bias ? bias[col] : 0.f;
            float b1 = bias ? bias[col + 1] : 0.f;
#pragma unroll
            for (int half = 0; half < 2; half++) {
                const long long rr = (long long)(row + half * 8) * ldc + col + coff;
                float v0 = acc[mt][nt][half * 2 + 0] + b0;
                float v1 = acc[mt][nt][half * 2 + 1] + b1;
                if (doRelu) { v0 = fmaxf(v0, 0.f); v1 = fmaxf(v1, 0.f); }
                if (Cf) {
                    *reinterpret_cast<float2*>(Cf + rr) = make_float2(v0, v1);
                } else {
                    __half2 hp;
                    hp.x = __float2half_rn(v0);
                    hp.y = __float2half_rn(v1);
                    *reinterpret_cast<__half2*>(Ch + rr) = hp;
                }
            }
        }
}

// fp32 -> fp16 rounding (vectorized)
__global__ void to_half_kernel(const float4* __restrict__ in,
                               __half* __restrict__ out, int n4)
{
    for (long long i = blockIdx.x * blockDim.x + threadIdx.x; i < n4;
         i += (long long)gridDim.x * blockDim.x) {
        float4 v = in[i];
        __half2 a, b;
        a.x = __float2half_rn(v.x); a.y = __float2half_rn(v.y);
        b.x = __float2half_rn(v.z); b.y = __float2half_rn(v.w);
        reinterpret_cast<__half2*>(out)[2 * i]     = a;
        reinterpret_cast<__half2*>(out)[2 * i + 1] = b;
    }
}

__global__ void avg_softmax_kernel(const __half* __restrict__ xh,
                                   const float* __restrict__ embed,
                                   float* __restrict__ ew)
{
    __shared__ float avg_s[DD];
    __shared__ float lg[EE_N];

    const int g = blockIdx.x;
    const int d = threadIdx.x;
    const int b = g >> 7;
    const int n = (g >> 3) & 15;
    const int h = g & 7;

    const long long base = (long long)(b * SS_ + n * SEGLEN) * HID + h * DD + d;
    float s = 0.f;
#pragma unroll 8
    for (int l = 0; l < SEGLEN; l++)
        s += __half2float(xh[base + (long long)l * HID]);
    avg_s[d] = s * (1.f / (float)SEGLEN);
    __syncthreads();

    if (d < EE_N) {
        float a = 0.f;
        for (int dd = 0; dd < DD; dd++) a += avg_s[dd] * embed[dd * EE_N + d];
        lg[d] = a;
    }
    __syncthreads();

    if (d == 0) {
        float mx = lg[0];
        for (int e = 1; e < EE_N; e++) mx = fmaxf(mx, lg[e]);
        float ex[EE_N], ssum = 0.f;
        for (int e = 0; e < EE_N; e++) { ex[e] = expf(lg[e] - mx); ssum += ex[e]; }
        float inv = 1.f / ssum;
        for (int e = 0; e < EE_N; e++) ew[g * EE_N + e] = ex[e] * inv;
    }
}

__global__ void mix_kernel(const float* __restrict__ ew,
                           const float* __restrict__ fl1,
                           const float* __restrict__ fl2,
                           __half* __restrict__ m1, __half* __restrict__ m2)
{
    __shared__ float w_s[NGROUP * EE_N];
    const int t = threadIdx.x;
    const float* src = blockIdx.y ? fl2 : fl1;
    __half* dst = blockIdx.y ? m2 : m1;
    const long long p = (long long)blockIdx.x * 128 + t;

    for (int idx = t; idx < NGROUP * EE_N; idx += 128) {
        int g = idx >> 4;
        int n = (g >> 3) & 15;
        int gs = (n > 0) ? (g - HEADS) : g;
        w_s[idx] = ew[gs * EE_N + (idx & 15)];
    }
    float flr[EE_N];
#pragma unroll
    for (int e = 0; e < EE_N; e++) flr[e] = src[(long long)e * (II * DD) + p];
    __syncthreads();

    for (int g = 0; g < NGROUP; g++) {
        float acc = 0.f;
#pragma unroll
        for (int e = 0; e < EE_N; e++) acc = fmaf(w_s[g * EE_N + e], flr[e], acc);
        dst[(long long)g * (II * DD) + p] = __float2half_rn(acc);
    }
}

extern "C" void kernel_launch(void* const* d_in, const int* in_sizes, int n_in,
                              void* d_out, int out_size)
{
    const float* x       = (const float*)d_in[0];
    const float* W_mh    = (const float*)d_in[1];
    const float* b_mh    = (const float*)d_in[2];
    const float* W_merge = (const float*)d_in[3];
    const float* b_merge = (const float*)d_in[4];
    const float* embed   = (const float*)d_in[5];
    const float* fl1     = (const float*)d_in[6];
    const float* fl2     = (const float*)d_in[7];
    float* out = (float*)d_out;

    __half *xb, *wmh, *wmg, *xh, *m1, *m2, *hh, *y2;
    float* ew;
    cudaGetSymbolAddress((void**)&xb, g_xb);
    cudaGetSymbolAddress((void**)&wmh, g_wmh);
    cudaGetSymbolAddress((void**)&wmg, g_wmg);
    cudaGetSymbolAddress((void**)&xh, g_xh);
    cudaGetSymbolAddress((void**)&m1, g_m1);
    cudaGetSymbolAddress((void**)&m2, g_m2);
    cudaGetSymbolAddress((void**)&hh, g_h);
    cudaGetSymbolAddress((void**)&y2, g_y2);
    cudaGetSymbolAddress((void**)&ew, g_ew);

    cudaFuncSetAttribute(mma_gemm, cudaFuncAttributeMaxDynamicSharedMemorySize, SMEM_BYTES);

    // 0) round fp32 inputs to fp16
    to_half_kernel<<<2048, 256>>>((const float4*)x, xb, MROWS * HID / 4);
    to_half_kernel<<<256, 256>>>((const float4*)W_mh, wmh, HID * HID / 4);
    to_half_kernel<<<256, 256>>>((const float4*)W_merge, wmg, HID * HID / 4);

    // 1) xh = x @ W_mh^T + b_mh  (fp16 out)
    mma_gemm<<<dim3(HID / 128, MROWS / 128, 1), 256, SMEM_BYTES>>>(
        xb, wmh, xh, nullptr, b_mh,
        HID, HID, HID, HID, 0, 0, 0, 0);

    // 2) routing softmax
    avg_softmax_kernel<<<NGROUP, DD>>>(xh, embed, ew);

    // 3) causally-shifted expert mixing (fp16 out)
    mix_kernel<<<dim3(II * DD / 128, 2), 128>>>(ew, fl1, fl2, m1, m2);

    // 4) h = relu(X @ m1^T)  batched 512x: M=256,N=512,K=128
    mma_gemm<<<dim3(II / 128, SEGLEN / 128, NGROUP), 256, SMEM_BYTES>>>(
        xh, m1, hh, nullptr, nullptr,
        DD, DD, DD, II,
        (long long)SEGLEN * DD, (long long)II * DD, (long long)SEGLEN * II, 1);

    // 5) y2 = h @ m2^T  batched 512x: M=256,N=128,K=512
    mma_gemm<<<dim3(DD / 128, SEGLEN / 128, NGROUP), 256, SMEM_BYTES>>>(
        hh, m2, y2, nullptr, nullptr,
        II, II, II, DD,
        (long long)SEGLEN * II, (long long)DD * II, (long long)SEGLEN * DD, 0);

    // 6) out = y2 @ W_merge^T + b_merge  (fp32 out)
    mma_gemm<<<dim3(HID / 128, MROWS / 128, 1), 256, SMEM_BYTES>>>(
        y2, wmg, nullptr, out, b_merge,
        HID, HID, HID, HID, 0, 0, 0, 0);
}

// round 14
// speedup vs baseline: 1.0586x; 1.0586x over previous
#include <cuda_runtime.h>
#include <cuda_fp16.h>
#include <cstdint>

#define HID 1024
#define HEADS 8
#define DD 128
#define NSEG 16
#define SEGLEN 256
#define EE_N 16
#define II 512
#define NGROUP 512
#define MROWS 16384
#define SS_ 4096

__device__ __half g_xb[MROWS * HID];
__device__ __half g_wmh[HID * HID];
__device__ __half g_wmg[HID * HID];
__device__ __half g_xh[MROWS * HID];
__device__ float  g_ew[NGROUP * EE_N];
__device__ __half g_m1[NGROUP * II * DD];
__device__ __half g_m2[NGROUP * DD * II];
__device__ __half g_y2[MROWS * HID];

__device__ __forceinline__ uint32_t smem_u32(const void* p) {
    uint32_t a;
    asm("{ .reg .u64 t; cvta.to.shared.u64 t, %1; cvt.u32.u64 %0, t; }" : "=r"(a) : "l"(p));
    return a;
}
__device__ __forceinline__ void cp_async16(uint32_t dst, const void* src) {
    asm volatile("cp.async.cg.shared.global [%0], [%1], 16;" :: "r"(dst), "l"(src) : "memory");
}

#define LDSM4(r, ad) \
    asm volatile("ldmatrix.sync.aligned.m8n8.x4.shared.b16 {%0,%1,%2,%3}, [%4];" \
        : "=r"((r)[0]), "=r"((r)[1]), "=r"((r)[2]), "=r"((r)[3]) : "r"(ad))

#define MMA(c, a, b) \
    asm volatile("mma.sync.aligned.m16n8k16.row.col.f32.f16.f16.f32 " \
        "{%0,%1,%2,%3},{%4,%5,%6,%7},{%8,%9},{%0,%1,%2,%3};" \
        : "+f"((c)[0]), "+f"((c)[1]), "+f"((c)[2]), "+f"((c)[3]) \
        : "r"((a)[0]), "r"((a)[1]), "r"((a)[2]), "r"((a)[3]), "r"((b)[0]), "r"((b)[1]))

// generic GEMM: 128B rows, pitch 144 ((9r)%8=r%8 -> conflict-free)
#define RPITCH 144
#define PLANE  (128 * RPITCH)          // 18432
#define STAGE  (2 * PLANE)             // 36864
#define SMEM_BYTES (3 * STAGE)         // 110592; 2 CTAs/SM (regs<=128)

#define COMMIT_EMPTY() asm volatile("cp.async.commit_group;" ::: "memory")

// ------------------- generic GEMM (R11 engine, unchanged) ------------------
__global__ __launch_bounds__(256)
void mma_gemm(const __half* __restrict__ A, const __half* __restrict__ B,
              __half* __restrict__ Ch, float* __restrict__ Cf,
              const float* __restrict__ bias,
              int K, int lda, int ldb, int ldc,
              long long aB, long long bB, long long cB, int doRelu)
{
    extern __shared__ char dsm[];
    const int tid  = threadIdx.x;
    const int lane = tid & 31;
    const int warp = tid >> 5;
    const int wm   = warp & 1;
    const int wn   = warp >> 1;

    const long long gz = blockIdx.z;
    A += gz * aB;
    B += gz * bB;
    const long long coff = gz * cB;
    const int m0 = blockIdx.y * 128;
    const int n0 = blockIdx.x * 128;

    const uint32_t sb = smem_u32(dsm);
    const int NK = K >> 6;

    float acc[4][4][4];
#pragma unroll
    for (int i = 0; i < 4; i++)
#pragma unroll
        for (int j = 0; j < 4; j++)
#pragma unroll
            for (int q = 0; q < 4; q++) acc[i][j][q] = 0.f;

    const __half* srcP[8];
    uint32_t dstOff[8];
#pragma unroll
    for (int it = 0; it < 8; it++) {
        int idx = it * 256 + tid;
        int pl = idx >> 10;
        int r  = (idx >> 3) & 127;
        int ch = idx & 7;
        srcP[it] = (pl ? B + (long long)(n0 + r) * ldb
                       : A + (long long)(m0 + r) * lda) + ch * 8;
        dstOff[it] = pl * PLANE + r * RPITCH + ch * 16;
    }

#define ISSUE(kt, st)                                                          \
    do {                                                                       \
        const int koff_ = (kt) << 6;                                           \
        const uint32_t db_ = sb + (st) * STAGE;                                \
        _Pragma("unroll")                                                      \
        for (int it = 0; it < 8; it++)                                         \
            cp_async16(db_ + dstOff[it], srcP[it] + koff_);                    \
        asm volatile("cp.async.commit_group;" ::: "memory");                   \
    } while (0)

    const int rowOffA = (lane & 7) + ((lane >> 3) & 1) * 8;
    const int kOffA   = ((lane >> 4) & 1) * 8;
    const int rowOffB = (lane & 7) + ((lane >> 4) & 1) * 8;
    const int kOffB   = ((lane >> 3) & 1) * 8;

    ISSUE(0, 0);
    if (NK > 1) { ISSUE(1, 1); } else { COMMIT_EMPTY(); }

    int stR = 0, stW = 2;
    for (int kt = 0; kt < NK; kt++) {
        asm volatile("cp.async.wait_group 1;" ::: "memory");
        __syncthreads();
        if (kt + 2 < NK) { ISSUE(kt + 2, stW); } else { COMMIT_EMPTY(); }

        const uint32_t base = sb + stR * STAGE;
#pragma unroll
        for (int ks = 0; ks < 4; ks++) {
            uint32_t a_f[4][4], b_f[4][2];
#pragma unroll
            for (int mt = 0; mt < 4; mt++) {
                uint32_t ad = base + (wm * 64 + mt * 16 + rowOffA) * RPITCH
                            + (ks * 16 + kOffA) * 2;
                LDSM4(a_f[mt], ad);
            }
#pragma unroll
            for (int pr = 0; pr < 2; pr++) {
                uint32_t bd = base + PLANE
                            + (wn * 32 + pr * 16 + rowOffB) * RPITCH
                            + (ks * 16 + kOffB) * 2;
                uint32_t r4[4];
                LDSM4(r4, bd);
                b_f[pr * 2][0] = r4[0];     b_f[pr * 2][1] = r4[1];
                b_f[pr * 2 + 1][0] = r4[2]; b_f[pr * 2 + 1][1] = r4[3];
            }
#pragma unroll
            for (int mt = 0; mt < 4; mt++)
#pragma unroll
                for (int nt = 0; nt < 4; nt++)
                    MMA(acc[mt][nt], a_f[mt], b_f[nt]);
        }
        stR = (stR == 2) ? 0 : stR + 1;
        stW = (stW == 2) ? 0 : stW + 1;
    }

    const int rq = lane >> 2;
    const int cq = (lane & 3) * 2;
#pragma unroll
    for (int mt = 0; mt < 4; mt++)
#pragma unroll
        for (int nt = 0; nt < 4; nt++) {
            const int row = m0 + wm * 64 + mt * 16 + rq;
            const int col = n0 + wn * 32 + nt * 8 + cq;
            float b0 = bias ? bias[col] : 0.f;
            float b1 = bias ? bias[col + 1] : 0.f;
#pragma unroll
            for (int half = 0; half < 2; half++) {
                const long long rr = (long long)(row + half * 8) * ldc + col + coff;
                float v0 = acc[mt][nt][half * 2 + 0] + b0;
                float v1 = acc[mt][nt][half * 2 + 1] + b1;
                if (doRelu) { v0 = fmaxf(v0, 0.f); v1 = fmaxf(v1, 0.f); }
                if (Cf) {
                    *reinterpret_cast<float2*>(Cf + rr) = make_float2(v0, v1);
                } else {
                    __half2 hp;
                    hp.x = __float2half_rn(v0);
                    hp.y = __float2half_rn(v1);
                    *reinterpret_cast<__half2*>(Ch + rr) = hp;
                }
            }
        }
}

// ------------------- fused per-group FFN: y2 = relu(X@m1^T)@m2^T -----------
// 256B data rows, pitch 272 ((17r)%8=r%8 -> conflict-free ldmatrix; h-store
// banks (68r+c/2)%32 all distinct).
#define FP      272
#define FPLANE  (128 * FP)                 // 34816
#define F_X     0
#define F_M(s)  (FPLANE + (s) * 2 * FPLANE)  // m1 at +0, m2 at +FPLANE; s in {0,1}
#define F_H     (FPLANE + 4 * FPLANE)        // 174080
#define F_SMEM  (F_H + FPLANE)               // 208896 (<227KB, 1 CTA/SM)
#define FTHREADS 512

__global__ __launch_bounds__(FTHREADS)
void fused_ffn(const __half* __restrict__ xh, const __half* __restrict__ m1,
               const __half* __restrict__ m2, __half* __restrict__ y2)
{
    extern __shared__ char dsm[];
    const int tid  = threadIdx.x;
    const int lane = tid & 31;
    const int warp = tid >> 5;
    const int wm   = warp & 3;        // 0..3 : 32-row slab
    const int wn   = warp >> 2;       // 0..3 : 32-col slab
    const int g    = blockIdx.y;
    const int mrow0 = blockIdx.x * 128;

    const uint32_t sb = smem_u32(dsm);
    const __half* xbase  = xh + (long long)g * 32768 + (long long)mrow0 * 128;
    const __half* m1base = m1 + (long long)g * 65536;
    const __half* m2base = m2 + (long long)g * 65536;

    float yacc[2][4][4];
#pragma unroll
    for (int i = 0; i < 2; i++)
#pragma unroll
        for (int j = 0; j < 4; j++)
#pragma unroll
            for (int q = 0; q < 4; q++) yacc[i][j][q] = 0.f;

    // m1 chunk c: rows i=c*128..+127, 128 d-cols (256B/row), contiguous.
    // m2 chunk c: 128 d-rows, i-cols c*128..+127 out of 512 (row stride 1024B).
#define FISSUE_M(c, st)                                                        \
    do {                                                                       \
        const __half* m1c_ = m1base + (c) * 16384;                             \
        const __half* m2c_ = m2base + (c) * 128;                               \
        const uint32_t d1_ = sb + F_M(st);                                     \
        _Pragma("unroll")                                                      \
        for (int it = 0; it < 4; it++) {                                       \
            int idx = it * 512 + tid;                                          \
            int r = idx >> 4, c2 = idx & 15;                                   \
            cp_async16(d1_ + r * FP + c2 * 16, m1c_ + idx * 8);                \
            cp_async16(d1_ + FPLANE + r * FP + c2 * 16,                        \
                       m2c_ + r * 512 + c2 * 8);                               \
        }                                                                      \
        asm volatile("cp.async.commit_group;" ::: "memory");                   \
    } while (0)

    // X tile: 128 rows x 256B
#pragma unroll
    for (int it = 0; it < 4; it++) {
        int idx = it * 512 + tid;
        int r = idx >> 4, c2 = idx & 15;
        cp_async16(sb + F_X + r * FP + c2 * 16, xbase + idx * 8);
    }
    FISSUE_M(0, 0);

    const int rowOffA = (lane & 7) + ((lane >> 3) & 1) * 8;
    const int kOffA   = ((lane >> 4) & 1) * 8;
    const int rowOffB = (lane & 7) + ((lane >> 4) & 1) * 8;
    const int kOffB   = ((lane >> 3) & 1) * 8;
    const int rq = lane >> 2;
    const int cq = (lane & 3) * 2;

    for (int c = 0; c < 4; c++) {
        if (c + 1 < 4) {
            FISSUE_M(c + 1, (c + 1) & 1);
            asm volatile("cp.async.wait_group 1;" ::: "memory");
        } else {
            asm volatile("cp.async.wait_group 0;" ::: "memory");
        }
        __syncthreads();

        const uint32_t bm1 = sb + F_M(c & 1);
        const uint32_t bm2 = bm1 + FPLANE;

        // GEMM A: h_chunk = X @ m1_chunk^T  (K = d = 128)
        float hacc[2][4][4];
#pragma unroll
        for (int i = 0; i < 2; i++)
#pragma unroll
            for (int j = 0; j < 4; j++)
#pragma unroll
                for (int q = 0; q < 4; q++) hacc[i][j][q] = 0.f;

#pragma unroll
        for (int ks = 0; ks < 8; ks++) {
            uint32_t a_f[2][4], b_f[4][2];
#pragma unroll
            for (int mt = 0; mt < 2; mt++) {
                uint32_t ad = sb + F_X + (wm * 32 + mt * 16 + rowOffA) * FP
                            + (ks * 16 + kOffA) * 2;
                LDSM4(a_f[mt], ad);
            }
#pragma unroll
            for (int pr = 0; pr < 2; pr++) {
                uint32_t bd = bm1 + (wn * 32 + pr * 16 + rowOffB) * FP
                            + (ks * 16 + kOffB) * 2;
                uint32_t r4[4];
                LDSM4(r4, bd);
                b_f[pr * 2][0] = r4[0];     b_f[pr * 2][1] = r4[1];
                b_f[pr * 2 + 1][0] = r4[2]; b_f[pr * 2 + 1][1] = r4[3];
            }
#pragma unroll
            for (int mt = 0; mt < 2; mt++)
#pragma unroll
                for (int nt = 0; nt < 4; nt++)
                    MMA(hacc[mt][nt], a_f[mt], b_f[nt]);
        }

        // relu + fp16 round + store h_chunk to smem
#pragma unroll
        for (int mt = 0; mt < 2; mt++)
#pragma unroll
            for (int nt = 0; nt < 4; nt++)
#pragma unroll
                for (int half = 0; half < 2; half++) {
                    int row = wm * 32 + mt * 16 + rq + half * 8;
                    int col = wn * 32 + nt * 8 + cq;
                    __half2 hp;
                    hp.x = __float2half_rn(fmaxf(hacc[mt][nt][half * 2 + 0], 0.f));
                    hp.y = __float2half_rn(fmaxf(hacc[mt][nt][half * 2 + 1], 0.f));
                    *reinterpret_cast<__half2*>(dsm + F_H + row * FP + col * 2) = hp;
                }
        __syncthreads();

        // GEMM B: y2 += h_chunk @ m2_chunk^T  (K = i = 128)
#pragma unroll
        for (int ks = 0; ks < 8; ks++) {
            uint32_t a_f[2][4], b_f[4][2];
#pragma unroll
            for (int mt = 0; mt < 2; mt++) {
                uint32_t ad = sb + F_H + (wm * 32 + mt * 16 + rowOffA) * FP
                            + (ks * 16 + kOffA) * 2;
                LDSM4(a_f[mt], ad);
            }
#pragma unroll
            for (int pr = 0; pr < 2; pr++) {
                uint32_t bd = bm2 + (wn * 32 + pr * 16 + rowOffB) * FP
                            + (ks * 16 + kOffB) * 2;
                uint32_t r4[4];
                LDSM4(r4, bd);
                b_f[pr * 2][0] = r4[0];     b_f[pr * 2][1] = r4[1];
                b_f[pr * 2 + 1][0] = r4[2]; b_f[pr * 2 + 1][1] = r4[3];
            }
#pragma unroll
            for (int mt = 0; mt < 2; mt++)
#pragma unroll
                for (int nt = 0; nt < 4; nt++)
                    MMA(yacc[mt][nt], a_f[mt], b_f[nt]);
        }
        __syncthreads();
    }

    // epilogue: y2 fp16
    __half* ybase = y2 + (long long)g * 32768 + (long long)mrow0 * 128;
#pragma unroll
    for (int mt = 0; mt < 2; mt++)
#pragma unroll
        for (int nt = 0; nt < 4; nt++)
#pragma unroll
            for (int half = 0; half < 2; half++) {
                int row = wm * 32 + mt * 16 + rq + half * 8;
                int col = wn * 32 + nt * 8 + cq;
                __half2 hp;
                hp.x = __float2half_rn(yacc[mt][nt][half * 2 + 0]);
                hp.y = __float2half_rn(yacc[mt][nt][half * 2 + 1]);
                *reinterpret_cast<__half2*>(ybase + row * 128 + col) = hp;
            }
}

// ------------------- small kernels (unchanged) -----------------------------
__global__ void to_half_kernel(const float4* __restrict__ in,
                               __half* __restrict__ out, int n4)
{
    for (long long i = blockIdx.x * blockDim.x + threadIdx.x; i < n4;
         i += (long long)gridDim.x * blockDim.x) {
        float4 v = in[i];
        __half2 a, b;
        a.x = __float2half_rn(v.x); a.y = __float2half_rn(v.y);
        b.x = __float2half_rn(v.z); b.y = __float2half_rn(v.w);
        reinterpret_cast<__half2*>(out)[2 * i]     = a;
        reinterpret_cast<__half2*>(out)[2 * i + 1] = b;
    }
}

__global__ void avg_softmax_kernel(const __half* __restrict__ xh,
                                   const float* __restrict__ embed,
                                   float* __restrict__ ew)
{
    __shared__ float avg_s[DD];
    __shared__ float lg[EE_N];

    const int g = blockIdx.x;
    const int d = threadIdx.x;
    const int b = g >> 7;
    const int n = (g >> 3) & 15;
    const int h = g & 7;

    const long long base = (long long)(b * SS_ + n * SEGLEN) * HID + h * DD + d;
    float s = 0.f;
#pragma unroll 8
    for (int l = 0; l < SEGLEN; l++)
        s += __half2float(xh[base + (long long)l * HID]);
    avg_s[d] = s * (1.f / (float)SEGLEN);
    __syncthreads();

    if (d < EE_N) {
        float a = 0.f;
        for (int dd = 0; dd < DD; dd++) a += avg_s[dd] * embed[dd * EE_N + d];
        lg[d] = a;
    }
    __syncthreads();

    if (d == 0) {
        float mx = lg[0];
        for (int e = 1; e < EE_N; e++) mx = fmaxf(mx, lg[e]);
        float ex[EE_N], ssum = 0.f;
        for (int e = 0; e < EE_N; e++) { ex[e] = expf(lg[e] - mx); ssum += ex[e]; }
        float inv = 1.f / ssum;
        for (int e = 0; e < EE_N; e++) ew[g * EE_N + e] = ex[e] * inv;
    }
}

__global__ void mix_kernel(const float* __restrict__ ew,
                           const float* __restrict__ fl1,
                           const float* __restrict__ fl2,
                           __half* __restrict__ m1, __half* __restrict__ m2)
{
    __shared__ float w_s[NGROUP * EE_N];
    const int t = threadIdx.x;
    const float* src = blockIdx.y ? fl2 : fl1;
    __half* dst = blockIdx.y ? m2 : m1;
    const long long p = (long long)blockIdx.x * 128 + t;

    for (int idx = t; idx < NGROUP * EE_N; idx += 128) {
        int g = idx >> 4;
        int n = (g >> 3) & 15;
        int gs = (n > 0) ? (g - HEADS) : g;
        w_s[idx] = ew[gs * EE_N + (idx & 15)];
    }
    float flr[EE_N];
#pragma unroll
    for (int e = 0; e < EE_N; e++) flr[e] = src[(long long)e * (II * DD) + p];
    __syncthreads();

    for (int g = 0; g < NGROUP; g++) {
        float acc = 0.f;
#pragma unroll
        for (int e = 0; e < EE_N; e++) acc = fmaf(w_s[g * EE_N + e], flr[e], acc);
        dst[(long long)g * (II * DD) + p] = __float2half_rn(acc);
    }
}

extern "C" void kernel_launch(void* const* d_in, const int* in_sizes, int n_in,
                              void* d_out, int out_size)
{
    const float* x       = (const float*)d_in[0];
    const float* W_mh    = (const float*)d_in[1];
    const float* b_mh    = (const float*)d_in[2];
    const float* W_merge = (const float*)d_in[3];
    const float* b_merge = (const float*)d_in[4];
    const float* embed   = (const float*)d_in[5];
    const float* fl1     = (const float*)d_in[6];
    const float* fl2     = (const float*)d_in[7];
    float* out = (float*)d_out;

    __half *xb, *wmh, *wmg, *xh, *m1, *m2, *y2;
    float* ew;
    cudaGetSymbolAddress((void**)&xb, g_xb);
    cudaGetSymbolAddress((void**)&wmh, g_wmh);
    cudaGetSymbolAddress((void**)&wmg, g_wmg);
    cudaGetSymbolAddress((void**)&xh, g_xh);
    cudaGetSymbolAddress((void**)&m1, g_m1);
    cudaGetSymbolAddress((void**)&m2, g_m2);
    cudaGetSymbolAddress((void**)&y2, g_y2);
    cudaGetSymbolAddress((void**)&ew, g_ew);

    cudaFuncSetAttribute(mma_gemm, cudaFuncAttributeMaxDynamicSharedMemorySize, SMEM_BYTES);
    cudaFuncSetAttribute(fused_ffn, cudaFuncAttributeMaxDynamicSharedMemorySize, F_SMEM);

    // 0) round fp32 inputs to fp16
    to_half_kernel<<<2048, 256>>>((const float4*)x, xb, MROWS * HID / 4);
    to_half_kernel<<<256, 256>>>((const float4*)W_mh, wmh, HID * HID / 4);
    to_half_kernel<<<256, 256>>>((const float4*)W_merge, wmg, HID * HID / 4);

    // 1) xh = x @ W_mh^T + b_mh  (fp16 out)
    mma_gemm<<<dim3(HID / 128, MROWS / 128, 1), 256, SMEM_BYTES>>>(
        xb, wmh, xh, nullptr, b_mh,
        HID, HID, HID, HID, 0, 0, 0, 0);

    // 2) routing softmax
    avg_softmax_kernel<<<NGROUP, DD>>>(xh, embed, ew);

    // 3) causally-shifted expert mixing (fp16 out)
    mix_kernel<<<dim3(II * DD / 128, 2), 128>>>(ew, fl1, fl2, m1, m2);

    // 4+5) fused y2 = relu(X @ m1^T) @ m2^T per group
    fused_ffn<<<dim3(SEGLEN / 128, NGROUP), FTHREADS, F_SMEM>>>(xh, m1, m2, y2);

    // 6) out = y2 @ W_merge^T + b_merge  (fp32 out)
    mma_gemm<<<dim3(HID / 128, MROWS / 128, 1), 256, SMEM_BYTES>>>(
        y2, wmg, nullptr, out, b_merge,
        HID, HID, HID, HID, 0, 0, 0, 0);
}

// round 16
// speedup vs baseline: 1.1768x; 1.1117x over previous
#include <cuda_runtime.h>
#include <cuda_fp16.h>
#include <cstdint>

#define HID 1024
#define HEADS 8
#define DD 128
#define NSEG 16
#define SEGLEN 256
#define EE_N 16
#define II 512
#define NGROUP 512
#define MROWS 16384
#define SS_ 4096

__device__ __half g_xb[MROWS * HID];
__device__ __half g_wmh[HID * HID];
__device__ __half g_wmg[HID * HID];
__device__ __half g_xh[MROWS * HID];
__device__ float  g_ew[NGROUP * EE_N];
__device__ __half g_m1[NGROUP * II * DD];
__device__ __half g_m2[NGROUP * DD * II];
__device__ __half g_y2[MROWS * HID];

__device__ __forceinline__ uint32_t smem_u32(const void* p) {
    uint32_t a;
    asm("{ .reg .u64 t; cvta.to.shared.u64 t, %1; cvt.u32.u64 %0, t; }" : "=r"(a) : "l"(p));
    return a;
}
__device__ __forceinline__ void cp_async16(uint32_t dst, const void* src) {
    asm volatile("cp.async.cg.shared.global [%0], [%1], 16;" :: "r"(dst), "l"(src) : "memory");
}

#define LDSM4(r, ad) \
    asm volatile("ldmatrix.sync.aligned.m8n8.x4.shared.b16 {%0,%1,%2,%3}, [%4];" \
        : "=r"((r)[0]), "=r"((r)[1]), "=r"((r)[2]), "=r"((r)[3]) : "r"(ad))

#define MMA(c, a, b) \
    asm volatile("mma.sync.aligned.m16n8k16.row.col.f32.f16.f16.f32 " \
        "{%0,%1,%2,%3},{%4,%5,%6,%7},{%8,%9},{%0,%1,%2,%3};" \
        : "+f"((c)[0]), "+f"((c)[1]), "+f"((c)[2]), "+f"((c)[3]) \
        : "r"((a)[0]), "r"((a)[1]), "r"((a)[2]), "r"((a)[3]), "r"((b)[0]), "r"((b)[1]))

// generic GEMM: 128B rows, pitch 144 ((9r)%8=r%8 -> conflict-free)
#define RPITCH 144
#define PLANE  (128 * RPITCH)          // 18432
#define STAGE  (2 * PLANE)             // 36864
#define SMEM_BYTES (3 * STAGE)         // 110592; 2 CTAs/SM (regs<=128)

#define COMMIT_EMPTY() asm volatile("cp.async.commit_group;" ::: "memory")

// ------------------- generic GEMM (R11 engine, unchanged) ------------------
__global__ __launch_bounds__(256)
void mma_gemm(const __half* __restrict__ A, const __half* __restrict__ B,
              __half* __restrict__ Ch, float* __restrict__ Cf,
              const float* __restrict__ bias,
              int K, int lda, int ldb, int ldc,
              long long aB, long long bB, long long cB, int doRelu)
{
    extern __shared__ char dsm[];
    const int tid  = threadIdx.x;
    const int lane = tid & 31;
    const int warp = tid >> 5;
    const int wm   = warp & 1;
    const int wn   = warp >> 1;

    const long long gz = blockIdx.z;
    A += gz * aB;
    B += gz * bB;
    const long long coff = gz * cB;
    const int m0 = blockIdx.y * 128;
    const int n0 = blockIdx.x * 128;

    const uint32_t sb = smem_u32(dsm);
    const int NK = K >> 6;

    float acc[4][4][4];
#pragma unroll
    for (int i = 0; i < 4; i++)
#pragma unroll
        for (int j = 0; j < 4; j++)
#pragma unroll
            for (int q = 0; q < 4; q++) acc[i][j][q] = 0.f;

    const __half* srcP[8];
    uint32_t dstOff[8];
#pragma unroll
    for (int it = 0; it < 8; it++) {
        int idx = it * 256 + tid;
        int pl = idx >> 10;
        int r  = (idx >> 3) & 127;
        int ch = idx & 7;
        srcP[it] = (pl ? B + (long long)(n0 + r) * ldb
                       : A + (long long)(m0 + r) * lda) + ch * 8;
        dstOff[it] = pl * PLANE + r * RPITCH + ch * 16;
    }

#define ISSUE(kt, st)                                                          \
    do {                                                                       \
        const int koff_ = (kt) << 6;                                           \
        const uint32_t db_ = sb + (st) * STAGE;                                \
        _Pragma("unroll")                                                      \
        for (int it = 0; it < 8; it++)                                         \
            cp_async16(db_ + dstOff[it], srcP[it] + koff_);                    \
        asm volatile("cp.async.commit_group;" ::: "memory");                   \
    } while (0)

    const int rowOffA = (lane & 7) + ((lane >> 3) & 1) * 8;
    const int kOffA   = ((lane >> 4) & 1) * 8;
    const int rowOffB = (lane & 7) + ((lane >> 4) & 1) * 8;
    const int kOffB   = ((lane >> 3) & 1) * 8;

    ISSUE(0, 0);
    if (NK > 1) { ISSUE(1, 1); } else { COMMIT_EMPTY(); }

    int stR = 0, stW = 2;
    for (int kt = 0; kt < NK; kt++) {
        asm volatile("cp.async.wait_group 1;" ::: "memory");
        __syncthreads();
        if (kt + 2 < NK) { ISSUE(kt + 2, stW); } else { COMMIT_EMPTY(); }

        const uint32_t base = sb + stR * STAGE;
#pragma unroll
        for (int ks = 0; ks < 4; ks++) {
            uint32_t a_f[4][4], b_f[4][2];
#pragma unroll
            for (int mt = 0; mt < 4; mt++) {
                uint32_t ad = base + (wm * 64 + mt * 16 + rowOffA) * RPITCH
                            + (ks * 16 + kOffA) * 2;
                LDSM4(a_f[mt], ad);
            }
#pragma unroll
            for (int pr = 0; pr < 2; pr++) {
                uint32_t bd = base + PLANE
                            + (wn * 32 + pr * 16 + rowOffB) * RPITCH
                            + (ks * 16 + kOffB) * 2;
                uint32_t r4[4];
                LDSM4(r4, bd);
                b_f[pr * 2][0] = r4[0];     b_f[pr * 2][1] = r4[1];
                b_f[pr * 2 + 1][0] = r4[2]; b_f[pr * 2 + 1][1] = r4[3];
            }
#pragma unroll
            for (int mt = 0; mt < 4; mt++)
#pragma unroll
                for (int nt = 0; nt < 4; nt++)
                    MMA(acc[mt][nt], a_f[mt], b_f[nt]);
        }
        stR = (stR == 2) ? 0 : stR + 1;
        stW = (stW == 2) ? 0 : stW + 1;
    }

    const int rq = lane >> 2;
    const int cq = (lane & 3) * 2;
#pragma unroll
    for (int mt = 0; mt < 4; mt++)
#pragma unroll
        for (int nt = 0; nt < 4; nt++) {
            const int row = m0 + wm * 64 + mt * 16 + rq;
            const int col = n0 + wn * 32 + nt * 8 + cq;
            float b0 = bias ? bias[col] : 0.f;
            float b1 = bias ? bias[col + 1] : 0.f;
#pragma unroll
            for (int half = 0; half < 2; half++) {
                const long long rr = (long long)(row + half * 8) * ldc + col + coff;
                float v0 = acc[mt][nt][half * 2 + 0] + b0;
                float v1 = acc[mt][nt][half * 2 + 1] + b1;
                if (doRelu) { v0 = fmaxf(v0, 0.f); v1 = fmaxf(v1, 0.f); }
                if (Cf) {
                    *reinterpret_cast<float2*>(Cf + rr) = make_float2(v0, v1);
                } else {
                    __half2 hp;
                    hp.x = __float2half_rn(v0);
                    hp.y = __float2half_rn(v1);
                    *reinterpret_cast<__half2*>(Ch + rr) = hp;
                }
            }
        }
}

// ------------------- fused per-group FFN (R14, unchanged) ------------------
#define FP      272
#define FPLANE  (128 * FP)                 // 34816
#define F_X     0
#define F_M(s)  (FPLANE + (s) * 2 * FPLANE)
#define F_H     (FPLANE + 4 * FPLANE)
#define F_SMEM  (F_H + FPLANE)             // 208896
#define FTHREADS 512

__global__ __launch_bounds__(FTHREADS)
void fused_ffn(const __half* __restrict__ xh, const __half* __restrict__ m1,
               const __half* __restrict__ m2, __half* __restrict__ y2)
{
    extern __shared__ char dsm[];
    const int tid  = threadIdx.x;
    const int lane = tid & 31;
    const int warp = tid >> 5;
    const int wm   = warp & 3;
    const int wn   = warp >> 2;
    const int g    = blockIdx.y;
    const int mrow0 = blockIdx.x * 128;

    const uint32_t sb = smem_u32(dsm);
    const __half* xbase  = xh + (long long)g * 32768 + (long long)mrow0 * 128;
    const __half* m1base = m1 + (long long)g * 65536;
    const __half* m2base = m2 + (long long)g * 65536;

    float yacc[2][4][4];
#pragma unroll
    for (int i = 0; i < 2; i++)
#pragma unroll
        for (int j = 0; j < 4; j++)
#pragma unroll
            for (int q = 0; q < 4; q++) yacc[i][j][q] = 0.f;

#define FISSUE_M(c, st)                                                        \
    do {                                                                       \
        const __half* m1c_ = m1base + (c) * 16384;                             \
        const __half* m2c_ = m2base + (c) * 128;                               \
        const uint32_t d1_ = sb + F_M(st);                                     \
        _Pragma("unroll")                                                      \
        for (int it = 0; it < 4; it++) {                                       \
            int idx = it * 512 + tid;                                          \
            int r = idx >> 4, c2 = idx & 15;                                   \
            cp_async16(d1_ + r * FP + c2 * 16, m1c_ + idx * 8);                \
            cp_async16(d1_ + FPLANE + r * FP + c2 * 16,                        \
                       m2c_ + r * 512 + c2 * 8);                               \
        }                                                                      \
        asm volatile("cp.async.commit_group;" ::: "memory");                   \
    } while (0)

#pragma unroll
    for (int it = 0; it < 4; it++) {
        int idx = it * 512 + tid;
        int r = idx >> 4, c2 = idx & 15;
        cp_async16(sb + F_X + r * FP + c2 * 16, xbase + idx * 8);
    }
    FISSUE_M(0, 0);

    const int rowOffA = (lane & 7) + ((lane >> 3) & 1) * 8;
    const int kOffA   = ((lane >> 4) & 1) * 8;
    const int rowOffB = (lane & 7) + ((lane >> 4) & 1) * 8;
    const int kOffB   = ((lane >> 3) & 1) * 8;
    const int rq = lane >> 2;
    const int cq = (lane & 3) * 2;

    for (int c = 0; c < 4; c++) {
        if (c + 1 < 4) {
            FISSUE_M(c + 1, (c + 1) & 1);
            asm volatile("cp.async.wait_group 1;" ::: "memory");
        } else {
            asm volatile("cp.async.wait_group 0;" ::: "memory");
        }
        __syncthreads();

        const uint32_t bm1 = sb + F_M(c & 1);
        const uint32_t bm2 = bm1 + FPLANE;

        float hacc[2][4][4];
#pragma unroll
        for (int i = 0; i < 2; i++)
#pragma unroll
            for (int j = 0; j < 4; j++)
#pragma unroll
                for (int q = 0; q < 4; q++) hacc[i][j][q] = 0.f;

#pragma unroll
        for (int ks = 0; ks < 8; ks++) {
            uint32_t a_f[2][4], b_f[4][2];
#pragma unroll
            for (int mt = 0; mt < 2; mt++) {
                uint32_t ad = sb + F_X + (wm * 32 + mt * 16 + rowOffA) * FP
                            + (ks * 16 + kOffA) * 2;
                LDSM4(a_f[mt], ad);
            }
#pragma unroll
            for (int pr = 0; pr < 2; pr++) {
                uint32_t bd = bm1 + (wn * 32 + pr * 16 + rowOffB) * FP
                            + (ks * 16 + kOffB) * 2;
                uint32_t r4[4];
                LDSM4(r4, bd);
                b_f[pr * 2][0] = r4[0];     b_f[pr * 2][1] = r4[1];
                b_f[pr * 2 + 1][0] = r4[2]; b_f[pr * 2 + 1][1] = r4[3];
            }
#pragma unroll
            for (int mt = 0; mt < 2; mt++)
#pragma unroll
                for (int nt = 0; nt < 4; nt++)
                    MMA(hacc[mt][nt], a_f[mt], b_f[nt]);
        }

#pragma unroll
        for (int mt = 0; mt < 2; mt++)
#pragma unroll
            for (int nt = 0; nt < 4; nt++)
#pragma unroll
                for (int half = 0; half < 2; half++) {
                    int row = wm * 32 + mt * 16 + rq + half * 8;
                    int col = wn * 32 + nt * 8 + cq;
                    __half2 hp;
                    hp.x = __float2half_rn(fmaxf(hacc[mt][nt][half * 2 + 0], 0.f));
                    hp.y = __float2half_rn(fmaxf(hacc[mt][nt][half * 2 + 1], 0.f));
                    *reinterpret_cast<__half2*>(dsm + F_H + row * FP + col * 2) = hp;
                }
        __syncthreads();

#pragma unroll
        for (int ks = 0; ks < 8; ks++) {
            uint32_t a_f[2][4], b_f[4][2];
#pragma unroll
            for (int mt = 0; mt < 2; mt++) {
                uint32_t ad = sb + F_H + (wm * 32 + mt * 16 + rowOffA) * FP
                            + (ks * 16 + kOffA) * 2;
                LDSM4(a_f[mt], ad);
            }
#pragma unroll
            for (int pr = 0; pr < 2; pr++) {
                uint32_t bd = bm2 + (wn * 32 + pr * 16 + rowOffB) * FP
                            + (ks * 16 + kOffB) * 2;
                uint32_t r4[4];
                LDSM4(r4, bd);
                b_f[pr * 2][0] = r4[0];     b_f[pr * 2][1] = r4[1];
                b_f[pr * 2 + 1][0] = r4[2]; b_f[pr * 2 + 1][1] = r4[3];
            }
#pragma unroll
            for (int mt = 0; mt < 2; mt++)
#pragma unroll
                for (int nt = 0; nt < 4; nt++)
                    MMA(yacc[mt][nt], a_f[mt], b_f[nt]);
        }
        __syncthreads();
    }

    __half* ybase = y2 + (long long)g * 32768 + (long long)mrow0 * 128;
#pragma unroll
    for (int mt = 0; mt < 2; mt++)
#pragma unroll
        for (int nt = 0; nt < 4; nt++)
#pragma unroll
            for (int half = 0; half < 2; half++) {
                int row = wm * 32 + mt * 16 + rq + half * 8;
                int col = wn * 32 + nt * 8 + cq;
                __half2 hp;
                hp.x = __float2half_rn(yacc[mt][nt][half * 2 + 0]);
                hp.y = __float2half_rn(yacc[mt][nt][half * 2 + 1]);
                *reinterpret_cast<__half2*>(ybase + row * 128 + col) = hp;
            }
}

// ------------------- small kernels ----------------------------------------
__global__ void to_half_kernel(const float4* __restrict__ in,
                               __half* __restrict__ out, int n4)
{
    for (long long i = blockIdx.x * blockDim.x + threadIdx.x; i < n4;
         i += (long long)gridDim.x * blockDim.x) {
        float4 v = in[i];
        __half2 a, b;
        a.x = __float2half_rn(v.x); a.y = __float2half_rn(v.y);
        b.x = __float2half_rn(v.z); b.y = __float2half_rn(v.w);
        reinterpret_cast<__half2*>(out)[2 * i]     = a;
        reinterpret_cast<__half2*>(out)[2 * i + 1] = b;
    }
}

__global__ void avg_softmax_kernel(const __half* __restrict__ xh,
                                   const float* __restrict__ embed,
                                   float* __restrict__ ew)
{
    __shared__ float avg_s[DD];
    __shared__ float lg[EE_N];

    const int g = blockIdx.x;
    const int d = threadIdx.x;
    const int b = g >> 7;
    const int n = (g >> 3) & 15;
    const int h = g & 7;

    const long long base = (long long)(b * SS_ + n * SEGLEN) * HID + h * DD + d;
    float s = 0.f;
#pragma unroll 8
    for (int l = 0; l < SEGLEN; l++)
        s += __half2float(xh[base + (long long)l * HID]);
    avg_s[d] = s * (1.f / (float)SEGLEN);
    __syncthreads();

    if (d < EE_N) {
        float a = 0.f;
        for (int dd = 0; dd < DD; dd++) a += avg_s[dd] * embed[dd * EE_N + d];
        lg[d] = a;
    }
    __syncthreads();

    if (d == 0) {
        float mx = lg[0];
        for (int e = 1; e < EE_N; e++) mx = fmaxf(mx, lg[e]);
        float ex[EE_N], ssum = 0.f;
        for (int e = 0; e < EE_N; e++) { ex[e] = expf(lg[e] - mx); ssum += ex[e]; }
        float inv = 1.f / ssum;
        for (int e = 0; e < EE_N; e++) ew[g * EE_N + e] = ex[e] * inv;
    }
}

// mix v2: 4 positions/thread, float4 expert loads, 8B half4 stores.
// FMA order per output position unchanged (ascending e) -> bit-identical.
__global__ void mix_kernel(const float* __restrict__ ew,
                           const float* __restrict__ fl1,
                           const float* __restrict__ fl2,
                           __half* __restrict__ m1, __half* __restrict__ m2)
{
    __shared__ float w_s[NGROUP * EE_N];   // 32 KB
    const int t = threadIdx.x;             // 128 threads
    const float* src = blockIdx.y ? fl2 : fl1;
    __half* dst = blockIdx.y ? m2 : m1;
    const long long p = ((long long)blockIdx.x * 128 + t) * 4;   // 0..65532

    for (int idx = t; idx < NGROUP * EE_N; idx += 128) {
        int g = idx >> 4;
        int n = (g >> 3) & 15;
        int gs = (n > 0) ? (g - HEADS) : g;
        w_s[idx] = ew[gs * EE_N + (idx & 15)];
    }
    float4 flr[EE_N];
#pragma unroll
    for (int e = 0; e < EE_N; e++)
        flr[e] = *reinterpret_cast<const float4*>(src + (long long)e * (II * DD) + p);
    __syncthreads();

    for (int g = 0; g < NGROUP; g++) {
        float a0 = 0.f, a1 = 0.f, a2 = 0.f, a3 = 0.f;
#pragma unroll
        for (int e = 0; e < EE_N; e++) {
            float w = w_s[g * EE_N + e];
            a0 = fmaf(w, flr[e].x, a0);
            a1 = fmaf(w, flr[e].y, a1);
            a2 = fmaf(w, flr[e].z, a2);
            a3 = fmaf(w, flr[e].w, a3);
        }
        __half2 h0, h1;
        h0.x = __float2half_rn(a0); h0.y = __float2half_rn(a1);
        h1.x = __float2half_rn(a2); h1.y = __float2half_rn(a3);
        uint2 pk;
        pk.x = *reinterpret_cast<uint32_t*>(&h0);
        pk.y = *reinterpret_cast<uint32_t*>(&h1);
        *reinterpret_cast<uint2*>(dst + (long long)g * (II * DD) + p) = pk;
    }
}

extern "C" void kernel_launch(void* const* d_in, const int* in_sizes, int n_in,
                              void* d_out, int out_size)
{
    const float* x       = (const float*)d_in[0];
    const float* W_mh    = (const float*)d_in[1];
    const float* b_mh    = (const float*)d_in[2];
    const float* W_merge = (const float*)d_in[3];
    const float* b_merge = (const float*)d_in[4];
    const float* embed   = (const float*)d_in[5];
    const float* fl1     = (const float*)d_in[6];
    const float* fl2     = (const float*)d_in[7];
    float* out = (float*)d_out;

    __half *xb, *wmh, *wmg, *xh, *m1, *m2, *y2;
    float* ew;
    cudaGetSymbolAddress((void**)&xb, g_xb);
    cudaGetSymbolAddress((void**)&wmh, g_wmh);
    cudaGetSymbolAddress((void**)&wmg, g_wmg);
    cudaGetSymbolAddress((void**)&xh, g_xh);
    cudaGetSymbolAddress((void**)&m1, g_m1);
    cudaGetSymbolAddress((void**)&m2, g_m2);
    cudaGetSymbolAddress((void**)&y2, g_y2);
    cudaGetSymbolAddress((void**)&ew, g_ew);

    cudaFuncSetAttribute(mma_gemm, cudaFuncAttributeMaxDynamicSharedMemorySize, SMEM_BYTES);
    cudaFuncSetAttribute(fused_ffn, cudaFuncAttributeMaxDynamicSharedMemorySize, F_SMEM);

    to_half_kernel<<<2048, 256>>>((const float4*)x, xb, MROWS * HID / 4);
    to_half_kernel<<<256, 256>>>((const float4*)W_mh, wmh, HID * HID / 4);
    to_half_kernel<<<256, 256>>>((const float4*)W_merge, wmg, HID * HID / 4);

    mma_gemm<<<dim3(HID / 128, MROWS / 128, 1), 256, SMEM_BYTES>>>(
        xb, wmh, xh, nullptr, b_mh,
        HID, HID, HID, HID, 0, 0, 0, 0);

    avg_softmax_kernel<<<NGROUP, DD>>>(xh, embed, ew);

    // mix v2: 4 positions/thread -> grid (128, 2)
    mix_kernel<<<dim3(II * DD / 512, 2), 128>>>(ew, fl1, fl2, m1, m2);

    fused_ffn<<<dim3(SEGLEN / 128, NGROUP), FTHREADS, F_SMEM>>>(xh, m1, m2, y2);

    mma_gemm<<<dim3(HID / 128, MROWS / 128, 1), 256, SMEM_BYTES>>>(
        y2, wmg, nullptr, out, b_merge,
        HID, HID, HID, HID, 0, 0, 0, 0);
}